// round 2
// baseline (speedup 1.0000x reference)
#include <cuda_runtime.h>

#define DI  64
#define BR  128
#define BC  64
#define PSS 132   // stride (floats) for [64][BR]-shaped smem arrays (pad, 16B-aligned)
#define NTS 68    // stride for nb_t [d][j]
#define NRS 68    // stride for nb_row [j][e]

struct SmemT {
    float ps[64 * PSS];   // x_t[d][r], then p_t[j][r]
    float nbt[64 * NTS];  // nb tile transposed [d][j]
    float nbr[BC * NRS];  // nb tile row-major [j][e]
    float at[BC * PSS];   // attn_t [j][r]; reused as agg_t [e][r]
    float wv[64 * 64];    // A_T [d][j] at start; Wv_t [e][o] in epilogue
    float bvec[64];       // bp at start; bv in epilogue
};

__device__ float g_AT[DI * DI];
__device__ float g_bp[DI];

// A[j][d] = sum_t Wk[t][j] * Wq[t][d]  (= (Wk^T Wq)[j][d]); stored as g_AT[d*64+j]
// bp[j]   = sum_t Wk[t][j] * bq[t]
__global__ void prep_kernel(const float* __restrict__ Wq, const float* __restrict__ bq,
                            const float* __restrict__ Wk) {
    int tid = threadIdx.x;            // 256 threads
    int j = tid & 63;
    int dbase = (tid >> 6) << 4;      // 4 groups of 16 d
    for (int dd = 0; dd < 16; ++dd) {
        int d = dbase + dd;
        float s = 0.f;
        for (int t = 0; t < 64; ++t) s += Wk[t * 64 + j] * Wq[t * 64 + d];
        g_AT[d * 64 + j] = s;
    }
    if (tid < 64) {
        float s = 0.f;
        for (int t = 0; t < 64; ++t) s += Wk[t * 64 + tid] * bq[t];
        g_bp[tid] = s;
    }
}

__global__ void __launch_bounds__(256, 1)
gat_kernel(const float* __restrict__ x, const float* __restrict__ nb,
           const float* __restrict__ Wv, const float* __restrict__ bv,
           float* __restrict__ out, int N, int M) {
    extern __shared__ float smem_raw[];
    SmemT* s = reinterpret_cast<SmemT*>(smem_raw);
    const int tid = threadIdx.x;
    const int tx  = tid & 15;         // 16 column-threads
    const int ty  = tid >> 4;         // 16 row-groups
    const int tx4 = tx * 4, ty8 = ty * 8;
    const int n0  = blockIdx.x * BR;

    // ---- load A_T + bp into smem ----
    for (int i = tid; i < 64 * 64; i += 256) s->wv[i] = g_AT[i];
    if (tid < 64) s->bvec[tid] = g_bp[tid];

    // ---- load x tile transposed into ps: ps[d][r] (zero-pad OOB rows) ----
    for (int rr = (tid >> 4); rr < BR; rr += 16) {
        int row = n0 + rr;
        float4 v = make_float4(0.f, 0.f, 0.f, 0.f);
        if (row < N) v = *(const float4*)&x[(size_t)row * DI + tx4];
        s->ps[(tx4 + 0) * PSS + rr] = v.x;
        s->ps[(tx4 + 1) * PSS + rr] = v.y;
        s->ps[(tx4 + 2) * PSS + rr] = v.z;
        s->ps[(tx4 + 3) * PSS + rr] = v.w;
    }
    __syncthreads();

    // ---- GEMM0: p[r][j] = bp[j] + sum_d x_t[d][r] * A_T[d][j] ----
    float acc[8][4];
    {
        float bj[4];
        #pragma unroll
        for (int u = 0; u < 4; ++u) bj[u] = s->bvec[tx4 + u];
        #pragma unroll
        for (int v = 0; v < 8; ++v)
            #pragma unroll
            for (int u = 0; u < 4; ++u) acc[v][u] = bj[u];
        #pragma unroll 4
        for (int d = 0; d < DI; ++d) {
            float4 a0 = *(const float4*)&s->ps[d * PSS + ty8];
            float4 a1 = *(const float4*)&s->ps[d * PSS + ty8 + 4];
            float4 b  = *(const float4*)&s->wv[d * 64 + tx4];
            float av[8] = {a0.x, a0.y, a0.z, a0.w, a1.x, a1.y, a1.z, a1.w};
            float bb[4] = {b.x, b.y, b.z, b.w};
            #pragma unroll
            for (int v = 0; v < 8; ++v)
                #pragma unroll
                for (int u = 0; u < 4; ++u) acc[v][u] = fmaf(av[v], bb[u], acc[v][u]);
        }
    }
    __syncthreads();   // everyone done reading x_t before overwrite
    // write p transposed: p_t[j][r]
    #pragma unroll
    for (int u = 0; u < 4; ++u) {
        *(float4*)&s->ps[(tx4 + u) * PSS + ty8]     = make_float4(acc[0][u], acc[1][u], acc[2][u], acc[3][u]);
        *(float4*)&s->ps[(tx4 + u) * PSS + ty8 + 4] = make_float4(acc[4][u], acc[5][u], acc[6][u], acc[7][u]);
    }

    // ---- flash loop state ----
    float aggr[8][4];
    #pragma unroll
    for (int v = 0; v < 8; ++v)
        #pragma unroll
        for (int u = 0; u < 4; ++u) aggr[v][u] = 0.f;
    float mrow[8], lrow[8];
    #pragma unroll
    for (int v = 0; v < 8; ++v) { mrow[v] = -1e30f; lrow[v] = 0.f; }

    for (int mt = 0; mt < M; mt += BC) {
        __syncthreads();  // prev GEMM2 done reading nbr/at; p_t writes visible (iter 0)
        // ---- load nb tile: row-major + transposed ----
        for (int jr = (tid >> 4); jr < BC; jr += 16) {
            float4 v = *(const float4*)&nb[(size_t)(mt + jr) * DI + tx4];
            *(float4*)&s->nbr[jr * NRS + tx4] = v;
            s->nbt[(tx4 + 0) * NTS + jr] = v.x;
            s->nbt[(tx4 + 1) * NTS + jr] = v.y;
            s->nbt[(tx4 + 2) * NTS + jr] = v.z;
            s->nbt[(tx4 + 3) * NTS + jr] = v.w;
        }
        __syncthreads();

        // ---- GEMM1: S[r][j] = sum_d p_t[d][r] * nb_t[d][j] ----
        float S[8][4];
        #pragma unroll
        for (int v = 0; v < 8; ++v)
            #pragma unroll
            for (int u = 0; u < 4; ++u) S[v][u] = 0.f;
        #pragma unroll 4
        for (int d = 0; d < DI; ++d) {
            float4 a0 = *(const float4*)&s->ps[d * PSS + ty8];
            float4 a1 = *(const float4*)&s->ps[d * PSS + ty8 + 4];
            float4 b  = *(const float4*)&s->nbt[d * NTS + tx4];
            float av[8] = {a0.x, a0.y, a0.z, a0.w, a1.x, a1.y, a1.z, a1.w};
            float bb[4] = {b.x, b.y, b.z, b.w};
            #pragma unroll
            for (int v = 0; v < 8; ++v)
                #pragma unroll
                for (int u = 0; u < 4; ++u) S[v][u] = fmaf(av[v], bb[u], S[v][u]);
        }

        // ---- online softmax (per-row; 16-lane shfl reductions; S -> exp in place) ----
        #pragma unroll
        for (int v = 0; v < 8; ++v) {
            float tm = fmaxf(fmaxf(S[v][0], S[v][1]), fmaxf(S[v][2], S[v][3]));
            tm = fmaxf(tm, __shfl_xor_sync(0xFFFFFFFFu, tm, 8, 16));
            tm = fmaxf(tm, __shfl_xor_sync(0xFFFFFFFFu, tm, 4, 16));
            tm = fmaxf(tm, __shfl_xor_sync(0xFFFFFFFFu, tm, 2, 16));
            tm = fmaxf(tm, __shfl_xor_sync(0xFFFFFFFFu, tm, 1, 16));
            float mnew = fmaxf(mrow[v], tm);
            float sc = __expf(mrow[v] - mnew);
            float rs = 0.f;
            #pragma unroll
            for (int u = 0; u < 4; ++u) { S[v][u] = __expf(S[v][u] - mnew); rs += S[v][u]; }
            rs += __shfl_xor_sync(0xFFFFFFFFu, rs, 8, 16);
            rs += __shfl_xor_sync(0xFFFFFFFFu, rs, 4, 16);
            rs += __shfl_xor_sync(0xFFFFFFFFu, rs, 2, 16);
            rs += __shfl_xor_sync(0xFFFFFFFFu, rs, 1, 16);
            lrow[v] = lrow[v] * sc + rs;
            mrow[v] = mnew;
            #pragma unroll
            for (int u = 0; u < 4; ++u) aggr[v][u] *= sc;
        }

        // ---- write exp tile transposed: at[j][r] (packed STS.128 along r) ----
        #pragma unroll
        for (int u = 0; u < 4; ++u) {
            *(float4*)&s->at[(tx4 + u) * PSS + ty8]     = make_float4(S[0][u], S[1][u], S[2][u], S[3][u]);
            *(float4*)&s->at[(tx4 + u) * PSS + ty8 + 4] = make_float4(S[4][u], S[5][u], S[6][u], S[7][u]);
        }
        __syncthreads();

        // ---- GEMM2: agg[r][e] += sum_j at[j][r] * nbr[j][e] ----
        #pragma unroll 4
        for (int j = 0; j < BC; ++j) {
            float4 a0 = *(const float4*)&s->at[j * PSS + ty8];
            float4 a1 = *(const float4*)&s->at[j * PSS + ty8 + 4];
            float4 b  = *(const float4*)&s->nbr[j * NRS + tx4];
            float av[8] = {a0.x, a0.y, a0.z, a0.w, a1.x, a1.y, a1.z, a1.w};
            float bb[4] = {b.x, b.y, b.z, b.w};
            #pragma unroll
            for (int v = 0; v < 8; ++v)
                #pragma unroll
                for (int u = 0; u < 4; ++u) aggr[v][u] = fmaf(av[v], bb[u], aggr[v][u]);
        }
    }

    __syncthreads();  // all GEMM2 reads of `at` done
    // ---- normalize and stage agg_t[e][r] into at ----
    float inv[8];
    #pragma unroll
    for (int v = 0; v < 8; ++v) inv[v] = 1.0f / lrow[v];
    #pragma unroll
    for (int u = 0; u < 4; ++u) {
        *(float4*)&s->at[(tx4 + u) * PSS + ty8] =
            make_float4(aggr[0][u] * inv[0], aggr[1][u] * inv[1], aggr[2][u] * inv[2], aggr[3][u] * inv[3]);
        *(float4*)&s->at[(tx4 + u) * PSS + ty8 + 4] =
            make_float4(aggr[4][u] * inv[4], aggr[5][u] * inv[5], aggr[6][u] * inv[6], aggr[7][u] * inv[7]);
    }
    // load Wv transposed + bv (wv/bvec free since GEMM0)
    for (int i = tid; i < 64 * 64; i += 256) {
        int o = i >> 6, e = i & 63;
        s->wv[e * 64 + o] = Wv[i];
    }
    if (tid < 64) s->bvec[tid] = bv[tid];
    __syncthreads();

    // ---- GEMM3: out[r][o] = bv[o] + sum_e agg_t[e][r] * Wv_t[e][o] ----
    float O[8][4];
    {
        float bj[4];
        #pragma unroll
        for (int u = 0; u < 4; ++u) bj[u] = s->bvec[tx4 + u];
        #pragma unroll
        for (int v = 0; v < 8; ++v)
            #pragma unroll
            for (int u = 0; u < 4; ++u) O[v][u] = bj[u];
    }
    #pragma unroll 4
    for (int e = 0; e < 64; ++e) {
        float4 a0 = *(const float4*)&s->at[e * PSS + ty8];
        float4 a1 = *(const float4*)&s->at[e * PSS + ty8 + 4];
        float4 b  = *(const float4*)&s->wv[e * 64 + tx4];
        float av[8] = {a0.x, a0.y, a0.z, a0.w, a1.x, a1.y, a1.z, a1.w};
        float bb[4] = {b.x, b.y, b.z, b.w};
        #pragma unroll
        for (int v = 0; v < 8; ++v)
            #pragma unroll
            for (int u = 0; u < 4; ++u) O[v][u] = fmaf(av[v], bb[u], O[v][u]);
    }
    #pragma unroll
    for (int v = 0; v < 8; ++v) {
        int row = n0 + ty8 + v;
        if (row < N)
            *(float4*)&out[(size_t)row * DI + tx4] = make_float4(O[v][0], O[v][1], O[v][2], O[v][3]);
    }
}

extern "C" void kernel_launch(void* const* d_in, const int* in_sizes, int n_in,
                              void* d_out, int out_size) {
    const float* x  = (const float*)d_in[0];
    const float* nb = (const float*)d_in[1];
    const float* Wq = (const float*)d_in[2];
    const float* bq = (const float*)d_in[3];
    const float* Wk = (const float*)d_in[4];
    // d_in[5] = bk: constant-over-m contribution to logits, drops out of softmax
    const float* Wv = (const float*)d_in[6];
    const float* bv = (const float*)d_in[7];
    float* out = (float*)d_out;

    const int N = in_sizes[0] / DI;
    const int M = in_sizes[1] / DI;

    cudaFuncSetAttribute(gat_kernel, cudaFuncAttributeMaxDynamicSharedMemorySize,
                         (int)sizeof(SmemT));

    prep_kernel<<<1, 256>>>(Wq, bq, Wk);
    const int grid = (N + BR - 1) / BR;
    gat_kernel<<<grid, 256, sizeof(SmemT)>>>(x, nb, Wv, bv, out, N, M);
}

// round 3
// speedup vs baseline: 1.0439x; 1.0439x over previous
#include <cuda_runtime.h>

typedef unsigned long long ull;

#define DI 64
#define BR 128
#define BC 64

struct __align__(16) Smem {
    float ps[BR * 64];    // x -> p -> normalized agg   (row-major [r][d], no swizzle)
    float at[BR * 64];    // attn [r][j] row-major (no swizzle; GEMM2 a-loads broadcast)
    float nbr[BC * 64];   // nb tile row-major [j][d], d-quads swizzled by (j>>2)&7
    float nbt[DI * 64];   // nb tile transposed [d][j], j-quads swizzled by (d>>2)&7
    float aw[DI * 64];    // A [j][d] swizzled; later Wv [o][e] swizzled
    float bvec[64];       // bp, then bv
};

__device__ float g_A[DI * DI];   // A[j][d] = sum_t Wk[t][j] * Wq[t][d], row-major [j][d]
__device__ float g_bp[DI];       // bp[j]   = sum_t Wk[t][j] * bq[t]

__device__ __forceinline__ ull ffma2(ull a, ull b, ull c) {
    ull d; asm("fma.rn.f32x2 %0,%1,%2,%3;" : "=l"(d) : "l"(a), "l"(b), "l"(c)); return d;
}
__device__ __forceinline__ ull fmul2(ull a, ull b) {
    ull d; asm("mul.rn.f32x2 %0,%1,%2;" : "=l"(d) : "l"(a), "l"(b)); return d;
}
__device__ __forceinline__ ull pack2(float lo, float hi) {
    ull r; asm("mov.b64 %0,{%1,%2};" : "=l"(r) : "f"(lo), "f"(hi)); return r;
}
__device__ __forceinline__ float hadd2(ull v) {
    float lo, hi; asm("mov.b64 {%0,%1},%2;" : "=f"(lo), "=f"(hi) : "l"(v)); return lo + hi;
}

__global__ void prep_kernel(const float* __restrict__ Wq, const float* __restrict__ bq,
                            const float* __restrict__ Wk) {
    int tid = threadIdx.x;            // 256 threads
    int j = tid & 63;
    int dbase = (tid >> 6) << 4;
    for (int dd = 0; dd < 16; ++dd) {
        int d = dbase + dd;
        float s = 0.f;
        for (int t = 0; t < 64; ++t) s += Wk[t * 64 + j] * Wq[t * 64 + d];
        g_A[j * 64 + d] = s;
    }
    if (tid < 64) {
        float s = 0.f;
        for (int t = 0; t < 64; ++t) s += Wk[t * 64 + tid] * bq[t];
        g_bp[tid] = s;
    }
}

// Reduction-vectorized 8x4 micro-GEMM over a 64-long reduction dim (16 quads).
// A rows = ty8+v (stride 64, un-swizzled; loads are broadcasts within quarter-warps).
// B rows = tx4+u (stride 64, quads swizzled by sx=(row>>2)&7=tx&7; loads are bank-perms).
__device__ __forceinline__ void gemm_rv(const float* __restrict__ A, const float* __restrict__ B,
                                        int ty8, int tx4, int sx, ull acc2[8][4]) {
    #pragma unroll 4
    for (int q = 0; q < 16; ++q) {
        const int qa = q << 2;
        const int qb = (q ^ sx) << 2;
        ulonglong2 a[8], b[4];
        #pragma unroll
        for (int v = 0; v < 8; ++v) a[v] = *(const ulonglong2*)(A + (ty8 + v) * 64 + qa);
        #pragma unroll
        for (int u = 0; u < 4; ++u) b[u] = *(const ulonglong2*)(B + (tx4 + u) * 64 + qb);
        #pragma unroll
        for (int v = 0; v < 8; ++v)
            #pragma unroll
            for (int u = 0; u < 4; ++u) {
                acc2[v][u] = ffma2(a[v].x, b[u].x, acc2[v][u]);
                acc2[v][u] = ffma2(a[v].y, b[u].y, acc2[v][u]);
            }
    }
}

__global__ void __launch_bounds__(256, 1)
gat_kernel(const float* __restrict__ x, const float* __restrict__ nb,
           const float* __restrict__ Wv, const float* __restrict__ bv,
           float* __restrict__ out, int N, int M) {
    extern __shared__ float smem_raw[];
    Smem* s = reinterpret_cast<Smem*>(smem_raw);
    const int tid = threadIdx.x;
    const int tx  = tid & 15;
    const int ty  = tid >> 4;
    const int tx4 = tx << 2, ty8 = ty << 3;
    const int sx  = tx & 7;
    const int n0  = blockIdx.x * BR;

    // ---- prologue: A (swizzled) + bp + x tile (straight row-major) ----
    for (int i = tid; i < 64 * 64; i += 256) {
        int j = i >> 6, d = i & 63;
        s->aw[j * 64 + ((((d >> 2) ^ ((j >> 2) & 7)) << 2) | (d & 3))] = g_A[i];
    }
    if (tid < 64) s->bvec[tid] = g_bp[tid];
    for (int rr = ty; rr < BR; rr += 16) {
        int row = n0 + rr;
        float4 v = make_float4(0.f, 0.f, 0.f, 0.f);
        if (row < N) v = *(const float4*)&x[(size_t)row * DI + tx4];
        *(float4*)&s->ps[rr * 64 + tx4] = v;
    }
    __syncthreads();

    // ---- GEMM0: p[r][j] = bp[j] + sum_d x[r][d] * A[j][d] ----
    {
        ull acc2[8][4];
        #pragma unroll
        for (int u = 0; u < 4; ++u) {
            ull bias = pack2(s->bvec[tx4 + u], 0.f);
            #pragma unroll
            for (int v = 0; v < 8; ++v) acc2[v][u] = bias;
        }
        gemm_rv(s->ps, s->aw, ty8, tx4, sx, acc2);
        __syncthreads();   // all reads of x done before overwrite with p
        #pragma unroll
        for (int v = 0; v < 8; ++v)
            *(float4*)&s->ps[(ty8 + v) * 64 + tx4] =
                make_float4(hadd2(acc2[v][0]), hadd2(acc2[v][1]),
                            hadd2(acc2[v][2]), hadd2(acc2[v][3]));
    }

    // ---- flash loop state (aggr kept PACKED over j-parity across tiles) ----
    ull aggr[8][4];
    #pragma unroll
    for (int v = 0; v < 8; ++v)
        #pragma unroll
        for (int u = 0; u < 4; ++u) aggr[v][u] = 0ull;
    float mrow[8], lrow[8];
    #pragma unroll
    for (int v = 0; v < 8; ++v) { mrow[v] = -1e30f; lrow[v] = 0.f; }

    for (int mt = 0; mt < M; mt += BC) {
        __syncthreads();   // prior GEMM2 done with nbr/nbt/at; p visible (first iter)
        // ---- load nb tile: row-major (swizzled) + transposed (swizzled) ----
        for (int jr = ty; jr < BC; jr += 16) {
            float4 v = *(const float4*)&nb[(size_t)(mt + jr) * DI + tx4];
            *(float4*)&s->nbr[jr * 64 + ((tx ^ ((jr >> 2) & 7)) << 2)] = v;
            int col = (((jr >> 2) ^ sx) << 2) | (jr & 3);
            s->nbt[(tx4 + 0) * 64 + col] = v.x;
            s->nbt[(tx4 + 1) * 64 + col] = v.y;
            s->nbt[(tx4 + 2) * 64 + col] = v.z;
            s->nbt[(tx4 + 3) * 64 + col] = v.w;
        }
        __syncthreads();

        // ---- GEMM1: S[r][j] = sum_d p[r][d] * nb[j][d] ----
        ull acc2[8][4];
        #pragma unroll
        for (int v = 0; v < 8; ++v)
            #pragma unroll
            for (int u = 0; u < 4; ++u) acc2[v][u] = 0ull;
        gemm_rv(s->ps, s->nbr, ty8, tx4, sx, acc2);

        float S[8][4];
        #pragma unroll
        for (int v = 0; v < 8; ++v)
            #pragma unroll
            for (int u = 0; u < 4; ++u) S[v][u] = hadd2(acc2[v][u]);

        // ---- online softmax (16-lane shfl reductions) ----
        #pragma unroll
        for (int v = 0; v < 8; ++v) {
            float tm = fmaxf(fmaxf(S[v][0], S[v][1]), fmaxf(S[v][2], S[v][3]));
            tm = fmaxf(tm, __shfl_xor_sync(0xFFFFFFFFu, tm, 8, 16));
            tm = fmaxf(tm, __shfl_xor_sync(0xFFFFFFFFu, tm, 4, 16));
            tm = fmaxf(tm, __shfl_xor_sync(0xFFFFFFFFu, tm, 2, 16));
            tm = fmaxf(tm, __shfl_xor_sync(0xFFFFFFFFu, tm, 1, 16));
            float mnew = fmaxf(mrow[v], tm);
            float sc = __expf(mrow[v] - mnew);
            float rs = 0.f;
            #pragma unroll
            for (int u = 0; u < 4; ++u) { S[v][u] = __expf(S[v][u] - mnew); rs += S[v][u]; }
            rs += __shfl_xor_sync(0xFFFFFFFFu, rs, 8, 16);
            rs += __shfl_xor_sync(0xFFFFFFFFu, rs, 4, 16);
            rs += __shfl_xor_sync(0xFFFFFFFFu, rs, 2, 16);
            rs += __shfl_xor_sync(0xFFFFFFFFu, rs, 1, 16);
            lrow[v] = lrow[v] * sc + rs;
            mrow[v] = mnew;
            ull sc2 = pack2(sc, sc);
            #pragma unroll
            for (int u = 0; u < 4; ++u) aggr[v][u] = fmul2(aggr[v][u], sc2);
        }

        // ---- store attn row-major: at[r][j] (natural float4, conflict-free) ----
        #pragma unroll
        for (int v = 0; v < 8; ++v)
            *(float4*)&s->at[(ty8 + v) * 64 + tx4] =
                make_float4(S[v][0], S[v][1], S[v][2], S[v][3]);
        __syncthreads();

        // ---- GEMM2: aggr[r][e] += sum_j attn[r][j] * nbt[e][j] (into packed aggr) ----
        gemm_rv(s->at, s->nbt, ty8, tx4, sx, aggr);
    }

    // ---- epilogue: normalize agg -> ps; Wv (swizzled) -> aw; bv -> bvec ----
    float inv[8];
    #pragma unroll
    for (int v = 0; v < 8; ++v) inv[v] = 1.0f / lrow[v];
    #pragma unroll
    for (int v = 0; v < 8; ++v)
        *(float4*)&s->ps[(ty8 + v) * 64 + tx4] =
            make_float4(hadd2(aggr[v][0]) * inv[v], hadd2(aggr[v][1]) * inv[v],
                        hadd2(aggr[v][2]) * inv[v], hadd2(aggr[v][3]) * inv[v]);
    for (int i = tid; i < 64 * 64; i += 256) {
        int o = i >> 6, e = i & 63;
        s->aw[o * 64 + ((((e >> 2) ^ ((o >> 2) & 7)) << 2) | (e & 3))] = Wv[i];
    }
    if (tid < 64) s->bvec[tid] = bv[tid];
    __syncthreads();

    // ---- GEMM3: out[r][o] = bv[o] + sum_e agg[r][e] * Wv[o][e] ----
    {
        ull acc2[8][4];
        #pragma unroll
        for (int u = 0; u < 4; ++u) {
            ull bias = pack2(s->bvec[tx4 + u], 0.f);
            #pragma unroll
            for (int v = 0; v < 8; ++v) acc2[v][u] = bias;
        }
        gemm_rv(s->ps, s->aw, ty8, tx4, sx, acc2);
        #pragma unroll
        for (int v = 0; v < 8; ++v) {
            int row = n0 + ty8 + v;
            if (row < N)
                *(float4*)&out[(size_t)row * DI + tx4] =
                    make_float4(hadd2(acc2[v][0]), hadd2(acc2[v][1]),
                                hadd2(acc2[v][2]), hadd2(acc2[v][3]));
        }
    }
}

extern "C" void kernel_launch(void* const* d_in, const int* in_sizes, int n_in,
                              void* d_out, int out_size) {
    const float* x  = (const float*)d_in[0];
    const float* nb = (const float*)d_in[1];
    const float* Wq = (const float*)d_in[2];
    const float* bq = (const float*)d_in[3];
    const float* Wk = (const float*)d_in[4];
    // d_in[5] = bk: constant over m in the logits -> drops out of softmax
    const float* Wv = (const float*)d_in[6];
    const float* bv = (const float*)d_in[7];
    float* out = (float*)d_out;

    const int N = in_sizes[0] / DI;
    const int M = in_sizes[1] / DI;

    cudaFuncSetAttribute(gat_kernel, cudaFuncAttributeMaxDynamicSharedMemorySize,
                         (int)sizeof(Smem));

    prep_kernel<<<1, 256>>>(Wq, bq, Wk);
    const int grid = (N + BR - 1) / BR;
    gat_kernel<<<grid, 256, sizeof(Smem)>>>(x, nb, Wv, bv, out, N, M);
}